// round 1
// baseline (speedup 1.0000x reference)
#include <cuda_runtime.h>

// Problem constants
#define Bb 32
#define Tt 2000
#define DIN 512
#define HH 512
#define MM (Bb * Tt)            // 64000 rows
#define NCHUNK 40
#define LCHUNK 50               // Tt / NCHUNK
#define NSTAT 250
#define ROWS_PER_STAT 256       // MM / NSTAT

#define ALPHA_LO 0.8187307530779818f   // exp(-1/5)
#define ALPHA_HI 0.9607894391523232f   // exp(-1/25)
#define BN_EPS 1e-5f

// ---------------- scratch (device globals; no allocation allowed) ----------
__device__ float g_Wx[(size_t)MM * HH];                 // 131 MB
__device__ float g_part_sum[NSTAT * HH];
__device__ float g_part_sq[NSTAT * HH];
__device__ float g_pa[HH], g_poma[HH], g_pg[HH], g_pc[HH], g_paL[HH];
__device__ float g_chunkend[(size_t)NCHUNK * Bb * HH];
__device__ float g_start[(size_t)NCHUNK * Bb * HH];
__device__ float g_accpart[(size_t)NCHUNK * Bb * HH];

// ---------------- GEMM: C[m,n] = sum_k x[m,k] * W[n,k] + b[n] --------------
// 128x128 tile, BK=16, 256 threads, 8x8 per thread, f32x2 packed FMA.
__global__ __launch_bounds__(256, 2)
void gemm_bias(const float* __restrict__ A, const float* __restrict__ Wt,
               const float* __restrict__ bias)
{
    __shared__ float As[16][128 + 4];
    __shared__ float Ws[16][128 + 4];
    const int tid = threadIdx.x;
    const int m0 = blockIdx.y * 128;
    const int n0 = blockIdx.x * 128;
    const int tx = tid & 15;        // n direction
    const int ty = tid >> 4;        // m direction
    const int lr = tid >> 2;        // 0..63
    const int lc = (tid & 3) << 2;  // 0,4,8,12

    unsigned long long acc[4][8];   // 4 m-pairs x 8 n columns (f32x2)
#pragma unroll
    for (int i = 0; i < 4; i++)
#pragma unroll
        for (int j = 0; j < 8; j++) acc[i][j] = 0ull;

    for (int k0 = 0; k0 < DIN; k0 += 16) {
        __syncthreads();
#pragma unroll
        for (int r = 0; r < 2; r++) {
            float4 va = *(const float4*)(A + (size_t)(m0 + lr + 64 * r) * DIN + k0 + lc);
            As[lc + 0][lr + 64 * r] = va.x;
            As[lc + 1][lr + 64 * r] = va.y;
            As[lc + 2][lr + 64 * r] = va.z;
            As[lc + 3][lr + 64 * r] = va.w;
            float4 vw = *(const float4*)(Wt + (size_t)(n0 + lr + 64 * r) * DIN + k0 + lc);
            Ws[lc + 0][lr + 64 * r] = vw.x;
            Ws[lc + 1][lr + 64 * r] = vw.y;
            Ws[lc + 2][lr + 64 * r] = vw.z;
            Ws[lc + 3][lr + 64 * r] = vw.w;
        }
        __syncthreads();
#pragma unroll
        for (int kk = 0; kk < 16; kk++) {
            // a: 8 consecutive m values -> 4 natural f32x2 pairs (no MOVs)
            ulonglong2 av0 = *(const ulonglong2*)(&As[kk][ty * 8]);
            ulonglong2 av1 = *(const ulonglong2*)(&As[kk][ty * 8 + 4]);
            unsigned long long a2[4] = {av0.x, av0.y, av1.x, av1.y};
            const float* bp = &Ws[kk][tx * 8];
            unsigned long long bb[8];
#pragma unroll
            for (int j = 0; j < 8; j++) {
                unsigned int bu = __float_as_uint(bp[j]);
                asm("mov.b64 %0, {%1, %1};" : "=l"(bb[j]) : "r"(bu));
            }
#pragma unroll
            for (int j = 0; j < 8; j++)
#pragma unroll
                for (int i = 0; i < 4; i++)
                    asm("fma.rn.f32x2 %0, %1, %2, %0;"
                        : "+l"(acc[i][j]) : "l"(a2[i]), "l"(bb[j]));
        }
    }

    // epilogue: unpack pairs, add bias, store
    float4 bv0 = *(const float4*)(bias + n0 + tx * 8);
    float4 bv1 = *(const float4*)(bias + n0 + tx * 8 + 4);
    float bl[8] = {bv0.x, bv0.y, bv0.z, bv0.w, bv1.x, bv1.y, bv1.z, bv1.w};
#pragma unroll
    for (int i = 0; i < 4; i++) {
#pragma unroll
        for (int half = 0; half < 2; half++) {
            int m = m0 + ty * 8 + i * 2 + half;
            float out8[8];
#pragma unroll
            for (int j = 0; j < 8; j++) {
                uint2 u = *(uint2*)&acc[i][j];
                out8[j] = __uint_as_float(half ? u.y : u.x) + bl[j];
            }
            float4* dst = (float4*)(g_Wx + (size_t)m * HH + n0 + tx * 8);
            dst[0] = make_float4(out8[0], out8[1], out8[2], out8[3]);
            dst[1] = make_float4(out8[4], out8[5], out8[6], out8[7]);
        }
    }
}

// ---------------- BN stats stage 1: per-block partial sums -----------------
__global__ void stats_partial()
{
    const int blk = blockIdx.x;
    const int tid = threadIdx.x;
    float4 s = {0.f, 0.f, 0.f, 0.f};
    float4 q = {0.f, 0.f, 0.f, 0.f};
    const float* base = g_Wx + (size_t)blk * ROWS_PER_STAT * HH + tid * 4;
    for (int r = 0; r < ROWS_PER_STAT; r++) {
        float4 v = *(const float4*)(base + (size_t)r * HH);
        s.x += v.x; s.y += v.y; s.z += v.z; s.w += v.w;
        q.x = fmaf(v.x, v.x, q.x); q.y = fmaf(v.y, v.y, q.y);
        q.z = fmaf(v.z, v.z, q.z); q.w = fmaf(v.w, v.w, q.w);
    }
    *(float4*)(g_part_sum + blk * HH + tid * 4) = s;
    *(float4*)(g_part_sq + blk * HH + tid * 4) = q;
}

// ---------------- BN stats stage 2 + per-channel params --------------------
__global__ void bn_params(const float* __restrict__ alpha,
                          const float* __restrict__ gamma,
                          const float* __restrict__ beta)
{
    const int h = threadIdx.x;
    float s = 0.f, q = 0.f;
    for (int p = 0; p < NSTAT; p++) {
        s += g_part_sum[p * HH + h];
        q += g_part_sq[p * HH + h];
    }
    const float invN = 1.0f / (float)MM;
    float mean = s * invN;
    float var = q * invN - mean * mean;
    float rs = rsqrtf(var + BN_EPS);
    float gg = gamma[h] * rs;
    float cc = beta[h] - mean * gg;
    float a = fminf(fmaxf(alpha[h], ALPHA_LO), ALPHA_HI);
    float aL = 1.0f;
    for (int i = 0; i < LCHUNK; i++) aL *= a;
    g_pa[h] = a;
    g_poma[h] = 1.0f - a;
    g_pg[h] = gg;
    g_pc[h] = cc;
    g_paL[h] = aL;
}

// ---------------- Scan phase B1: zero-init local chunk endpoints -----------
__global__ __launch_bounds__(128)
void scan_carry()
{
    const int k = blockIdx.x, b = blockIdx.y, tid = threadIdx.x;
    const int h4 = tid * 4;
    float4 a   = *(const float4*)(g_pa + h4);
    float4 oma = *(const float4*)(g_poma + h4);
    float4 gg  = *(const float4*)(g_pg + h4);
    float4 cc  = *(const float4*)(g_pc + h4);
    float4 ut = {0.f, 0.f, 0.f, 0.f};
    const float* src = g_Wx + ((size_t)b * Tt + (size_t)k * LCHUNK) * HH + h4;
#pragma unroll 5
    for (int t = 0; t < LCHUNK; t++) {
        float4 w = *(const float4*)(src + (size_t)t * HH);
        float w0 = fmaf(gg.x, w.x, cc.x);
        float w1 = fmaf(gg.y, w.y, cc.y);
        float w2 = fmaf(gg.z, w.z, cc.z);
        float w3 = fmaf(gg.w, w.w, cc.w);
        ut.x = fmaf(a.x, ut.x, oma.x * w0);
        ut.y = fmaf(a.y, ut.y, oma.y * w1);
        ut.z = fmaf(a.z, ut.z, oma.z * w2);
        ut.w = fmaf(a.w, ut.w, oma.w * w3);
    }
    *(float4*)(g_chunkend + ((size_t)k * Bb + b) * HH + h4) = ut;
}

// ---------------- Combine: propagate true chunk-start states ---------------
__global__ void combine_carries(const float* __restrict__ ut0)
{
    const int b = blockIdx.x, h = threadIdx.x;
    const float aL = g_paL[h];
    float s = ut0[b * HH + h];
    g_start[(size_t)b * HH + h] = s;   // chunk 0 start
    for (int k = 0; k < NCHUNK - 1; k++) {
        s = fmaf(aL, s, g_chunkend[((size_t)k * Bb + b) * HH + h]);
        g_start[((size_t)(k + 1) * Bb + b) * HH + h] = s;
    }
}

// ---------------- Scan phase B2: exact recurrence + softmax accumulation ---
__global__ __launch_bounds__(128)
void scan_softmax()
{
    __shared__ float smax[4];
    __shared__ float ssum[4];
    const int k = blockIdx.x, b = blockIdx.y, tid = threadIdx.x;
    const int lane = tid & 31, wid = tid >> 5;
    const int h4 = tid * 4;
    float4 a   = *(const float4*)(g_pa + h4);
    float4 oma = *(const float4*)(g_poma + h4);
    float4 gg  = *(const float4*)(g_pg + h4);
    float4 cc  = *(const float4*)(g_pc + h4);
    float4 ut  = *(const float4*)(g_start + ((size_t)k * Bb + b) * HH + h4);
    float4 acc = {0.f, 0.f, 0.f, 0.f};
    const float* src = g_Wx + ((size_t)b * Tt + (size_t)k * LCHUNK) * HH + h4;

    for (int t = 0; t < LCHUNK; t++) {
        float4 w = *(const float4*)(src + (size_t)t * HH);
        float w0 = fmaf(gg.x, w.x, cc.x);
        float w1 = fmaf(gg.y, w.y, cc.y);
        float w2 = fmaf(gg.z, w.z, cc.z);
        float w3 = fmaf(gg.w, w.w, cc.w);
        ut.x = fmaf(a.x, ut.x, oma.x * w0);
        ut.y = fmaf(a.y, ut.y, oma.y * w1);
        ut.z = fmaf(a.z, ut.z, oma.z * w2);
        ut.w = fmaf(a.w, ut.w, oma.w * w3);

        // block max over 512 channels
        float m = fmaxf(fmaxf(ut.x, ut.y), fmaxf(ut.z, ut.w));
#pragma unroll
        for (int o = 16; o; o >>= 1) m = fmaxf(m, __shfl_xor_sync(0xffffffffu, m, o));
        if (lane == 0) smax[wid] = m;
        __syncthreads();
        float Mx = fmaxf(fmaxf(smax[0], smax[1]), fmaxf(smax[2], smax[3]));

        float e0 = __expf(ut.x - Mx);
        float e1 = __expf(ut.y - Mx);
        float e2 = __expf(ut.z - Mx);
        float e3 = __expf(ut.w - Mx);
        float sv = (e0 + e1) + (e2 + e3);
#pragma unroll
        for (int o = 16; o; o >>= 1) sv += __shfl_xor_sync(0xffffffffu, sv, o);
        if (lane == 0) ssum[wid] = sv;
        __syncthreads();
        float inv = 1.0f / ((ssum[0] + ssum[1]) + (ssum[2] + ssum[3]));

        acc.x = fmaf(e0, inv, acc.x);
        acc.y = fmaf(e1, inv, acc.y);
        acc.z = fmaf(e2, inv, acc.z);
        acc.w = fmaf(e3, inv, acc.w);
    }
    *(float4*)(g_accpart + ((size_t)k * Bb + b) * HH + h4) = acc;
}

// ---------------- Final deterministic reduction over chunks ----------------
__global__ void final_sum(float* __restrict__ out)
{
    const int b = blockIdx.x, h = threadIdx.x;
    float s = 0.f;
    for (int k = 0; k < NCHUNK; k++)
        s += g_accpart[((size_t)k * Bb + b) * HH + h];
    out[b * HH + h] = s;
}

// ---------------- launch ---------------------------------------------------
extern "C" void kernel_launch(void* const* d_in, const int* in_sizes, int n_in,
                              void* d_out, int out_size)
{
    const float* x     = (const float*)d_in[0];
    const float* W     = (const float*)d_in[1];
    const float* bias  = (const float*)d_in[2];
    const float* alpha = (const float*)d_in[3];
    const float* gamma = (const float*)d_in[4];
    const float* beta  = (const float*)d_in[5];
    const float* ut0   = (const float*)d_in[6];
    float* out = (float*)d_out;

    gemm_bias<<<dim3(HH / 128, MM / 128), 256>>>(x, W, bias);
    stats_partial<<<NSTAT, 128>>>();
    bn_params<<<1, HH>>>(alpha, gamma, beta);
    scan_carry<<<dim3(NCHUNK, Bb), 128>>>();
    combine_carries<<<Bb, HH>>>(ut0);
    scan_softmax<<<dim3(NCHUNK, Bb), 128>>>();
    final_sum<<<Bb, HH>>>(out);
}

// round 5
// speedup vs baseline: 2.4531x; 2.4531x over previous
#include <cuda_runtime.h>
#include <cuda_bf16.h>
#include <cstdint>

// Problem constants
#define Bb 32
#define Tt 2000
#define DIN 512
#define HH 512
#define MM (Bb * Tt)            // 64000 rows
#define NCHUNK 40
#define LCHUNK 50               // Tt / NCHUNK
#define NSTAT 250
#define ROWS_PER_STAT 256       // MM / NSTAT

#define ALPHA_LO 0.8187307530779818f   // exp(-1/5)
#define ALPHA_HI 0.9607894391523232f   // exp(-1/25)
#define BN_EPS 1e-5f

// tcgen05 is only legal on the arch-specific (sm_103a) compilation pass.
// The harness also runs a plain compute_103 PTX pass; stub it out there.
#if defined(__CUDA_ARCH__) && (defined(__CUDA_ARCH_FEAT_SM103_ALL) || \
    defined(__CUDA_ARCH_FEAT_SM100_ALL) || defined(__CUDA_ARCH_SPECIFIC__) || \
    defined(__CUDA_ARCH_FAMILY_SPECIFIC__))
#define TC_OK 1
#else
#define TC_OK 0
#endif

// ---------------- scratch (device globals; no allocation allowed) ----------
__device__ float g_Wx[(size_t)MM * HH];                 // 131 MB
__device__ __align__(16) __nv_bfloat16 g_Ahi[(size_t)MM * DIN];  // 65.5 MB
__device__ __align__(16) __nv_bfloat16 g_Alo[(size_t)MM * DIN];  // 65.5 MB
__device__ __align__(16) __nv_bfloat16 g_Whi[(size_t)HH * DIN];
__device__ __align__(16) __nv_bfloat16 g_Wlo[(size_t)HH * DIN];
__device__ float g_part_sum[NSTAT * HH];
__device__ float g_part_sq[NSTAT * HH];
__device__ float g_pa[HH], g_poma[HH], g_pg[HH], g_pc[HH], g_paL[HH];
__device__ float g_chunkend[(size_t)NCHUNK * Bb * HH];
__device__ float g_start[(size_t)NCHUNK * Bb * HH];
__device__ float g_accpart[(size_t)NCHUNK * Bb * HH];

// ======================= PTX helpers (inlined, arch-guarded) ===============
__device__ __forceinline__ uint32_t smem_u32(const void* p) {
    uint32_t a;
    asm("{ .reg .u64 t; cvta.to.shared.u64 t, %1; cvt.u32.u64 %0, t; }" : "=r"(a) : "l"(p));
    return a;
}
__device__ __forceinline__ uint32_t elect_one() {
    uint32_t pred;
    asm volatile("{\n\t.reg .pred p;\n\telect.sync _|p, 0xFFFFFFFF;\n\tselp.b32 %0, 1, 0, p;\n\t}" : "=r"(pred));
    return pred;
}
__device__ __forceinline__ void mbar_init(uint32_t a, uint32_t n) {
    asm volatile("mbarrier.init.shared.b64 [%0], %1;" :: "r"(a), "r"(n) : "memory");
}
__device__ __forceinline__ void mbar_wait(uint32_t a, uint32_t parity) {
    asm volatile(
        "{\n\t.reg .pred P;\n\t"
        "LW%=:\n\t"
        "mbarrier.try_wait.parity.acquire.cta.shared::cta.b64 P, [%0], %1, 0x989680;\n\t"
        "@P bra LD%=;\n\t"
        "bra LW%=;\n\t"
        "LD%=:\n\t}"
        :: "r"(a), "r"(parity) : "memory");
}
__device__ __forceinline__ void tc_alloc(uint32_t smem_addr, uint32_t ncols) {
#if TC_OK
    asm volatile("tcgen05.alloc.cta_group::1.sync.aligned.shared::cta.b32 [%0], %1;"
                 :: "r"(smem_addr), "r"(ncols) : "memory");
#endif
}
__device__ __forceinline__ void tc_relinq() {
#if TC_OK
    asm volatile("tcgen05.relinquish_alloc_permit.cta_group::1.sync.aligned;");
#endif
}
__device__ __forceinline__ void tc_dealloc(uint32_t tmem, uint32_t ncols) {
#if TC_OK
    asm volatile("tcgen05.dealloc.cta_group::1.sync.aligned.b32 %0, %1;" :: "r"(tmem), "r"(ncols));
#endif
}
__device__ __forceinline__ void tc_commit(uint32_t mbar) {
#if TC_OK
    asm volatile("tcgen05.commit.cta_group::1.mbarrier::arrive::one.shared::cluster.b64 [%0];"
                 :: "r"(mbar) : "memory");
#endif
}
__device__ __forceinline__ void fence_async_smem() {
    asm volatile("fence.proxy.async.shared::cta;" ::: "memory");
}
__device__ __forceinline__ void tc_fence_after() {
#if TC_OK
    asm volatile("tcgen05.fence::after_thread_sync;" ::: "memory");
#endif
}
__device__ __forceinline__ void tc_wait_ld() {
#if TC_OK
    asm volatile("tcgen05.wait::ld.sync.aligned;" ::: "memory");
#endif
}
// SS-mode bf16 MMA, cta_group::1
__device__ __forceinline__ void mma_f16_ss(uint32_t d, uint64_t ad, uint64_t bd,
                                           uint32_t idesc, uint32_t en) {
#if TC_OK
    asm volatile(
        "{\n\t.reg .pred p;\n\tsetp.ne.u32 p, %5, 0;\n\t"
        "tcgen05.mma.cta_group::1.kind::f16 [%0], %1, %2, %3, {%4,%4,%4,%4}, p;\n\t}"
        :: "r"(d), "l"(ad), "l"(bd), "r"(idesc), "r"(0u), "r"(en) : "memory");
#endif
}
__device__ __forceinline__ void ldtm_x32(uint32_t* r, uint32_t addr) {
#if TC_OK
    asm volatile(
        "tcgen05.ld.sync.aligned.32x32b.x32.b32 "
        "{%0, %1, %2, %3, %4, %5, %6, %7, %8, %9, %10, %11, %12, %13, %14, %15, "
        " %16, %17, %18, %19, %20, %21, %22, %23, %24, %25, %26, %27, %28, %29, %30, %31}, [%32];"
        : "=r"(r[0]), "=r"(r[1]), "=r"(r[2]), "=r"(r[3]), "=r"(r[4]), "=r"(r[5]), "=r"(r[6]), "=r"(r[7]),
          "=r"(r[8]), "=r"(r[9]), "=r"(r[10]), "=r"(r[11]), "=r"(r[12]), "=r"(r[13]), "=r"(r[14]), "=r"(r[15]),
          "=r"(r[16]), "=r"(r[17]), "=r"(r[18]), "=r"(r[19]), "=r"(r[20]), "=r"(r[21]), "=r"(r[22]), "=r"(r[23]),
          "=r"(r[24]), "=r"(r[25]), "=r"(r[26]), "=r"(r[27]), "=r"(r[28]), "=r"(r[29]), "=r"(r[30]), "=r"(r[31])
        : "r"(addr));
#else
    for (int i = 0; i < 32; i++) r[i] = 0u;
#endif
}
// SW128 K-major descriptor: version=1, LBO=1 (16B), SBO=64 (1024B), layout=SW128
#define SMEM_DESC_BASE_SW128 \
    ((uint64_t(2) << 61) | (uint64_t(1) << 46) | (uint64_t(64) << 32) | (uint64_t(1) << 16))
__device__ __forceinline__ uint64_t make_desc(uint32_t addr) {
    return SMEM_DESC_BASE_SW128 | ((uint64_t)(addr >> 4) & 0x3FFF);
}

// ======================= fp32 -> bf16 hi/lo conversion =====================
__device__ __forceinline__ uint32_t pack_hi2(float a, float b, float& ra, float& rb) {
    __nv_bfloat16 ha = __float2bfloat16(a), hb = __float2bfloat16(b);
    ra = a - __bfloat162float(ha);
    rb = b - __bfloat162float(hb);
    return ((uint32_t)__bfloat16_as_ushort(hb) << 16) | (uint32_t)__bfloat16_as_ushort(ha);
}
__device__ __forceinline__ uint32_t pack2(float a, float b) {
    return ((uint32_t)__bfloat16_as_ushort(__float2bfloat16(b)) << 16) |
           (uint32_t)__bfloat16_as_ushort(__float2bfloat16(a));
}

__global__ void convert_x(const float* __restrict__ x) {
    size_t i = ((size_t)blockIdx.x * 256 + threadIdx.x) * 4;
    float4 v = *(const float4*)(x + i);
    float r0, r1, r2, r3;
    uint32_t h01 = pack_hi2(v.x, v.y, r0, r1);
    uint32_t h23 = pack_hi2(v.z, v.w, r2, r3);
    uint32_t l01 = pack2(r0, r1);
    uint32_t l23 = pack2(r2, r3);
    *(uint2*)((uint16_t*)g_Ahi + i) = make_uint2(h01, h23);
    *(uint2*)((uint16_t*)g_Alo + i) = make_uint2(l01, l23);
}

__global__ void convert_W(const float* __restrict__ W) {
    size_t i = ((size_t)blockIdx.x * 256 + threadIdx.x) * 4;
    float4 v = *(const float4*)(W + i);
    float r0, r1, r2, r3;
    uint32_t h01 = pack_hi2(v.x, v.y, r0, r1);
    uint32_t h23 = pack_hi2(v.z, v.w, r2, r3);
    uint32_t l01 = pack2(r0, r1);
    uint32_t l23 = pack2(r2, r3);
    *(uint2*)((uint16_t*)g_Whi + i) = make_uint2(h01, h23);
    *(uint2*)((uint16_t*)g_Wlo + i) = make_uint2(l01, l23);
}

// ======================= tcgen05 GEMM ======================================
// Per CTA: M=128, N=512 (two N=256 MMAs, D = 512 TMEM cols), K: 24 chunks of 64
// (3 terms x 8 chunks): hi*Whi, lo*Whi, hi*Wlo. Double-buffered smem.
#define BK 64
#define NCHUNKS_K 24
#define SM_A0 1024u
#define SM_B0 17408u
#define SM_A1 82944u
#define SM_B1 99328u
#define SM_TOTAL 164864
// idesc: dtype=F32, atype=BF16, btype=BF16, N=256, M=128
#define GEMM_IDESC ((1u << 4) | (1u << 7) | (1u << 10) | (32u << 17) | (8u << 24))

__global__ __launch_bounds__(256, 1)
void gemm_tc(const float* __restrict__ bias)
{
    extern __shared__ char smem[];
    const uint32_t sb = smem_u32(smem);
    const int tid = threadIdx.x;
    const int wid = tid >> 5;
    const int lid = tid & 31;
    const int m0 = blockIdx.x * 128;

    if (wid == 0) {
        tc_alloc(sb + 0, 512);
        tc_relinq();
    }
    if (tid == 0) mbar_init(sb + 8, 1);
    __syncthreads();
    uint32_t tbase;
    asm volatile("ld.shared.b32 %0, [%1];" : "=r"(tbase) : "r"(sb + 0));

    // ---- tile loader: A 128x64 bf16 (16KB), B 512x64 bf16 (64KB), SW128 ----
    auto load_chunk = [&](int ci, int bufsel) {
        const int term = ci >> 3;
        const int k0 = (ci & 7) * BK;
        const __nv_bfloat16* Asrc = (term == 1) ? g_Alo : g_Ahi;
        const __nv_bfloat16* Bsrc = (term == 2) ? g_Wlo : g_Whi;
        char* abuf = smem + (bufsel ? SM_A1 : SM_A0);
        char* bbuf = smem + (bufsel ? SM_B1 : SM_B0);
#pragma unroll
        for (int i = 0; i < 4; i++) {                 // A: 1024 16B chunks
            int idx = i * 256 + tid;
            int row = idx >> 3, c = idx & 7;
            uint4 v = *(const uint4*)(Asrc + (size_t)(m0 + row) * DIN + k0 + c * 8);
            *(uint4*)(abuf + row * 128 + ((c ^ (row & 7)) * 16)) = v;
        }
#pragma unroll
        for (int i = 0; i < 16; i++) {                // B: 4096 16B chunks
            int idx = i * 256 + tid;
            int row = idx >> 3, c = idx & 7;
            uint4 v = *(const uint4*)(Bsrc + (size_t)row * DIN + k0 + c * 8);
            *(uint4*)(bbuf + row * 128 + ((c ^ (row & 7)) * 16)) = v;
        }
    };

    load_chunk(0, 0);
    __syncthreads();

    for (int ci = 0; ci < NCHUNKS_K; ci++) {
        const int bs = ci & 1;
        if (wid == 0) {
            fence_async_smem();
            if (elect_one()) {
                uint64_t ad = make_desc(sb + (bs ? SM_A1 : SM_A0));
                uint64_t bd0 = make_desc(sb + (bs ? SM_B1 : SM_B0));
                uint64_t bd1 = make_desc(sb + (bs ? SM_B1 : SM_B0) + 32768u);
#pragma unroll
                for (int ks = 0; ks < 4; ks++) {
                    uint32_t en = (ci > 0 || ks > 0) ? 1u : 0u;
                    mma_f16_ss(tbase + 0,   ad + ks * 2, bd0 + ks * 2, GEMM_IDESC, en);
                    mma_f16_ss(tbase + 256, ad + ks * 2, bd1 + ks * 2, GEMM_IDESC, en);
                }
                tc_commit(sb + 8);
            }
        }
        if (ci + 1 < NCHUNKS_K) load_chunk(ci + 1, bs ^ 1);
#if TC_OK
        mbar_wait(sb + 8, ci & 1);
#endif
        __syncthreads();
    }

    tc_fence_after();
    // ---- epilogue: warps 0-3 read 128 lanes x 512 cols, add bias, store ----
    if (wid < 4) {
        const int m = m0 + wid * 32 + lid;
        float* dst = g_Wx + (size_t)m * HH;
#pragma unroll 1
        for (int c0 = 0; c0 < HH; c0 += 32) {
            uint32_t r[32];
            ldtm_x32(r, tbase + c0);
            tc_wait_ld();
#pragma unroll
            for (int j = 0; j < 32; j += 4) {
                float4 bv = *(const float4*)(bias + c0 + j);
                float4 o;
                o.x = __uint_as_float(r[j + 0]) + bv.x;
                o.y = __uint_as_float(r[j + 1]) + bv.y;
                o.z = __uint_as_float(r[j + 2]) + bv.z;
                o.w = __uint_as_float(r[j + 3]) + bv.w;
                *(float4*)(dst + c0 + j) = o;
            }
        }
    }
    __syncthreads();
    if (wid == 0) {
        tc_dealloc(tbase, 512);
    }
}

// ---------------- BN stats stage 1: per-block partial sums -----------------
__global__ void stats_partial()
{
    const int blk = blockIdx.x;
    const int tid = threadIdx.x;
    float4 s = {0.f, 0.f, 0.f, 0.f};
    float4 q = {0.f, 0.f, 0.f, 0.f};
    const float* base = g_Wx + (size_t)blk * ROWS_PER_STAT * HH + tid * 4;
    for (int r = 0; r < ROWS_PER_STAT; r++) {
        float4 v = *(const float4*)(base + (size_t)r * HH);
        s.x += v.x; s.y += v.y; s.z += v.z; s.w += v.w;
        q.x = fmaf(v.x, v.x, q.x); q.y = fmaf(v.y, v.y, q.y);
        q.z = fmaf(v.z, v.z, q.z); q.w = fmaf(v.w, v.w, q.w);
    }
    *(float4*)(g_part_sum + blk * HH + tid * 4) = s;
    *(float4*)(g_part_sq + blk * HH + tid * 4) = q;
}

// ---------------- BN stats stage 2 + per-channel params --------------------
__global__ void bn_params(const float* __restrict__ alpha,
                          const float* __restrict__ gamma,
                          const float* __restrict__ beta)
{
    const int h = threadIdx.x;
    float s = 0.f, q = 0.f;
    for (int p = 0; p < NSTAT; p++) {
        s += g_part_sum[p * HH + h];
        q += g_part_sq[p * HH + h];
    }
    const float invN = 1.0f / (float)MM;
    float mean = s * invN;
    float var = q * invN - mean * mean;
    float rs = rsqrtf(var + BN_EPS);
    float gg = gamma[h] * rs;
    float cc = beta[h] - mean * gg;
    float a = fminf(fmaxf(alpha[h], ALPHA_LO), ALPHA_HI);
    float aL = 1.0f;
    for (int i = 0; i < LCHUNK; i++) aL *= a;
    g_pa[h] = a;
    g_poma[h] = 1.0f - a;
    g_pg[h] = gg;
    g_pc[h] = cc;
    g_paL[h] = aL;
}

// ---------------- Scan phase B1: zero-init local chunk endpoints -----------
__global__ __launch_bounds__(128)
void scan_carry()
{
    const int k = blockIdx.x, b = blockIdx.y, tid = threadIdx.x;
    const int h4 = tid * 4;
    float4 a   = *(const float4*)(g_pa + h4);
    float4 oma = *(const float4*)(g_poma + h4);
    float4 gg  = *(const float4*)(g_pg + h4);
    float4 cc  = *(const float4*)(g_pc + h4);
    float4 ut = {0.f, 0.f, 0.f, 0.f};
    const float* src = g_Wx + ((size_t)b * Tt + (size_t)k * LCHUNK) * HH + h4;
#pragma unroll 5
    for (int t = 0; t < LCHUNK; t++) {
        float4 w = *(const float4*)(src + (size_t)t * HH);
        float w0 = fmaf(gg.x, w.x, cc.x);
        float w1 = fmaf(gg.y, w.y, cc.y);
        float w2 = fmaf(gg.z, w.z, cc.z);
        float w3 = fmaf(gg.w, w.w, cc.w);
        ut.x = fmaf(a.x, ut.x, oma.x * w0);
        ut.y = fmaf(a.y, ut.y, oma.y * w1);
        ut.z = fmaf(a.z, ut.z, oma.z * w2);
        ut.w = fmaf(a.w, ut.w, oma.w * w3);
    }
    *(float4*)(g_chunkend + ((size_t)k * Bb + b) * HH + h4) = ut;
}

// ---------------- Combine: propagate true chunk-start states ---------------
__global__ void combine_carries(const float* __restrict__ ut0)
{
    const int b = blockIdx.x, h = threadIdx.x;
    const float aL = g_paL[h];
    float s = ut0[b * HH + h];
    g_start[(size_t)b * HH + h] = s;   // chunk 0 start
    for (int k = 0; k < NCHUNK - 1; k++) {
        s = fmaf(aL, s, g_chunkend[((size_t)k * Bb + b) * HH + h]);
        g_start[((size_t)(k + 1) * Bb + b) * HH + h] = s;
    }
}

// ---------------- Scan phase B2: exact recurrence + softmax accumulation ---
__global__ __launch_bounds__(128)
void scan_softmax()
{
    __shared__ float smax[4];
    __shared__ float ssum[4];
    const int k = blockIdx.x, b = blockIdx.y, tid = threadIdx.x;
    const int lane = tid & 31, wid = tid >> 5;
    const int h4 = tid * 4;
    float4 a   = *(const float4*)(g_pa + h4);
    float4 oma = *(const float4*)(g_poma + h4);
    float4 gg  = *(const float4*)(g_pg + h4);
    float4 cc  = *(const float4*)(g_pc + h4);
    float4 ut  = *(const float4*)(g_start + ((size_t)k * Bb + b) * HH + h4);
    float4 acc = {0.f, 0.f, 0.f, 0.f};
    const float* src = g_Wx + ((size_t)b * Tt + (size_t)k * LCHUNK) * HH + h4;

    for (int t = 0; t < LCHUNK; t++) {
        float4 w = *(const float4*)(src + (size_t)t * HH);
        float w0 = fmaf(gg.x, w.x, cc.x);
        float w1 = fmaf(gg.y, w.y, cc.y);
        float w2 = fmaf(gg.z, w.z, cc.z);
        float w3 = fmaf(gg.w, w.w, cc.w);
        ut.x = fmaf(a.x, ut.x, oma.x * w0);
        ut.y = fmaf(a.y, ut.y, oma.y * w1);
        ut.z = fmaf(a.z, ut.z, oma.z * w2);
        ut.w = fmaf(a.w, ut.w, oma.w * w3);

        // block max over 512 channels
        float m = fmaxf(fmaxf(ut.x, ut.y), fmaxf(ut.z, ut.w));
#pragma unroll
        for (int o = 16; o; o >>= 1) m = fmaxf(m, __shfl_xor_sync(0xffffffffu, m, o));
        if (lane == 0) smax[wid] = m;
        __syncthreads();
        float Mx = fmaxf(fmaxf(smax[0], smax[1]), fmaxf(smax[2], smax[3]));

        float e0 = __expf(ut.x - Mx);
        float e1 = __expf(ut.y - Mx);
        float e2 = __expf(ut.z - Mx);
        float e3 = __expf(ut.w - Mx);
        float sv = (e0 + e1) + (e2 + e3);
#pragma unroll
        for (int o = 16; o; o >>= 1) sv += __shfl_xor_sync(0xffffffffu, sv, o);
        if (lane == 0) ssum[wid] = sv;
        __syncthreads();
        float inv = 1.0f / ((ssum[0] + ssum[1]) + (ssum[2] + ssum[3]));

        acc.x = fmaf(e0, inv, acc.x);
        acc.y = fmaf(e1, inv, acc.y);
        acc.z = fmaf(e2, inv, acc.z);
        acc.w = fmaf(e3, inv, acc.w);
    }
    *(float4*)(g_accpart + ((size_t)k * Bb + b) * HH + h4) = acc;
}

// ---------------- Final deterministic reduction over chunks ----------------
__global__ void final_sum(float* __restrict__ out)
{
    const int b = blockIdx.x, h = threadIdx.x;
    float s = 0.f;
    for (int k = 0; k < NCHUNK; k++)
        s += g_accpart[((size_t)k * Bb + b) * HH + h];
    out[b * HH + h] = s;
}

// ---------------- launch ---------------------------------------------------
extern "C" void kernel_launch(void* const* d_in, const int* in_sizes, int n_in,
                              void* d_out, int out_size)
{
    const float* x     = (const float*)d_in[0];
    const float* W     = (const float*)d_in[1];
    const float* bias  = (const float*)d_in[2];
    const float* alpha = (const float*)d_in[3];
    const float* gamma = (const float*)d_in[4];
    const float* beta  = (const float*)d_in[5];
    const float* ut0   = (const float*)d_in[6];
    float* out = (float*)d_out;

    cudaFuncSetAttribute(gemm_tc, cudaFuncAttributeMaxDynamicSharedMemorySize, SM_TOTAL);

    convert_x<<<(MM * DIN) / (256 * 4), 256>>>(x);
    convert_W<<<(HH * DIN) / (256 * 4), 256>>>(W);
    gemm_tc<<<MM / 128, 256, SM_TOTAL>>>(bias);
    stats_partial<<<NSTAT, 128>>>();
    bn_params<<<1, HH>>>(alpha, gamma, beta);
    scan_carry<<<dim3(NCHUNK, Bb), 128>>>();
    combine_carries<<<Bb, HH>>>(ut0);
    scan_softmax<<<dim3(NCHUNK, Bb), 128>>>();
    final_sum<<<Bb, HH>>>(out);
}

// round 7
// speedup vs baseline: 3.2960x; 1.3436x over previous
#include <cuda_runtime.h>
#include <cuda_bf16.h>
#include <cstdint>

// Problem constants
#define Bb 32
#define Tt 2000
#define DIN 512
#define HH 512
#define MM (Bb * Tt)            // 64000 rows
#define NCHUNK 40
#define LCHUNK 50               // Tt / NCHUNK
#define NSTAT (NCHUNK * Bb)     // 1280 stats partials (one per carry block)
#define NRED 40                 // second-level stats partials

#define ALPHA_LO 0.8187307530779818f   // exp(-1/5)
#define ALPHA_HI 0.9607894391523232f   // exp(-1/25)
#define BN_EPS 1e-5f

// tcgen05 is only legal on the arch-specific (sm_103a) compilation pass.
#if defined(__CUDA_ARCH__) && (defined(__CUDA_ARCH_FEAT_SM103_ALL) || \
    defined(__CUDA_ARCH_FEAT_SM100_ALL) || defined(__CUDA_ARCH_SPECIFIC__) || \
    defined(__CUDA_ARCH_FAMILY_SPECIFIC__))
#define TC_OK 1
#else
#define TC_OK 0
#endif

// ---------------- scratch (device globals; no allocation allowed) ----------
__device__ float g_Wx[(size_t)MM * HH];                 // 131 MB
__device__ __align__(16) __nv_bfloat16 g_Whi[(size_t)HH * DIN];
__device__ __align__(16) __nv_bfloat16 g_Wlo[(size_t)HH * DIN];
__device__ float g_part_sum[NSTAT * HH];
__device__ float g_part_sq[NSTAT * HH];
__device__ float g_red_sum[NRED * HH];
__device__ float g_red_sq[NRED * HH];
__device__ float g_pa[HH], g_poma[HH], g_pg[HH], g_pc[HH], g_paL[HH];
__device__ float g_chunkend[(size_t)NCHUNK * Bb * HH];   // RAW (pre-BN) endpoints
__device__ float g_start[(size_t)NCHUNK * Bb * HH];
__device__ float g_accpart[(size_t)NCHUNK * Bb * HH];

// ======================= PTX helpers (arch-guarded) ========================
__device__ __forceinline__ uint32_t smem_u32(const void* p) {
    uint32_t a;
    asm("{ .reg .u64 t; cvta.to.shared.u64 t, %1; cvt.u32.u64 %0, t; }" : "=r"(a) : "l"(p));
    return a;
}
__device__ __forceinline__ uint32_t elect_one() {
    uint32_t pred;
    asm volatile("{\n\t.reg .pred p;\n\telect.sync _|p, 0xFFFFFFFF;\n\tselp.b32 %0, 1, 0, p;\n\t}" : "=r"(pred));
    return pred;
}
__device__ __forceinline__ void mbar_init(uint32_t a, uint32_t n) {
    asm volatile("mbarrier.init.shared.b64 [%0], %1;" :: "r"(a), "r"(n) : "memory");
}
__device__ __forceinline__ void mbar_wait(uint32_t a, uint32_t parity) {
    asm volatile(
        "{\n\t.reg .pred P;\n\t"
        "LW%=:\n\t"
        "mbarrier.try_wait.parity.acquire.cta.shared::cta.b64 P, [%0], %1, 0x989680;\n\t"
        "@P bra LD%=;\n\t"
        "bra LW%=;\n\t"
        "LD%=:\n\t}"
        :: "r"(a), "r"(parity) : "memory");
}
__device__ __forceinline__ void tc_alloc(uint32_t smem_addr, uint32_t ncols) {
#if TC_OK
    asm volatile("tcgen05.alloc.cta_group::1.sync.aligned.shared::cta.b32 [%0], %1;"
                 :: "r"(smem_addr), "r"(ncols) : "memory");
#endif
}
__device__ __forceinline__ void tc_relinq() {
#if TC_OK
    asm volatile("tcgen05.relinquish_alloc_permit.cta_group::1.sync.aligned;");
#endif
}
__device__ __forceinline__ void tc_dealloc(uint32_t tmem, uint32_t ncols) {
#if TC_OK
    asm volatile("tcgen05.dealloc.cta_group::1.sync.aligned.b32 %0, %1;" :: "r"(tmem), "r"(ncols));
#endif
}
__device__ __forceinline__ void tc_commit(uint32_t mbar) {
#if TC_OK
    asm volatile("tcgen05.commit.cta_group::1.mbarrier::arrive::one.shared::cluster.b64 [%0];"
                 :: "r"(mbar) : "memory");
#endif
}
__device__ __forceinline__ void fence_async_smem() {
    asm volatile("fence.proxy.async.shared::cta;" ::: "memory");
}
__device__ __forceinline__ void tc_fence_after() {
#if TC_OK
    asm volatile("tcgen05.fence::after_thread_sync;" ::: "memory");
#endif
}
__device__ __forceinline__ void tc_wait_ld() {
#if TC_OK
    asm volatile("tcgen05.wait::ld.sync.aligned;" ::: "memory");
#endif
}
__device__ __forceinline__ void mma_f16_ss(uint32_t d, uint64_t ad, uint64_t bd,
                                           uint32_t idesc, uint32_t en) {
#if TC_OK
    asm volatile(
        "{\n\t.reg .pred p;\n\tsetp.ne.u32 p, %5, 0;\n\t"
        "tcgen05.mma.cta_group::1.kind::f16 [%0], %1, %2, %3, {%4,%4,%4,%4}, p;\n\t}"
        :: "r"(d), "l"(ad), "l"(bd), "r"(idesc), "r"(0u), "r"(en) : "memory");
#endif
}
__device__ __forceinline__ void ldtm_x32(uint32_t* r, uint32_t addr) {
#if TC_OK
    asm volatile(
        "tcgen05.ld.sync.aligned.32x32b.x32.b32 "
        "{%0, %1, %2, %3, %4, %5, %6, %7, %8, %9, %10, %11, %12, %13, %14, %15, "
        " %16, %17, %18, %19, %20, %21, %22, %23, %24, %25, %26, %27, %28, %29, %30, %31}, [%32];"
        : "=r"(r[0]), "=r"(r[1]), "=r"(r[2]), "=r"(r[3]), "=r"(r[4]), "=r"(r[5]), "=r"(r[6]), "=r"(r[7]),
          "=r"(r[8]), "=r"(r[9]), "=r"(r[10]), "=r"(r[11]), "=r"(r[12]), "=r"(r[13]), "=r"(r[14]), "=r"(r[15]),
          "=r"(r[16]), "=r"(r[17]), "=r"(r[18]), "=r"(r[19]), "=r"(r[20]), "=r"(r[21]), "=r"(r[22]), "=r"(r[23]),
          "=r"(r[24]), "=r"(r[25]), "=r"(r[26]), "=r"(r[27]), "=r"(r[28]), "=r"(r[29]), "=r"(r[30]), "=r"(r[31])
        : "r"(addr));
#else
    for (int i = 0; i < 32; i++) r[i] = 0u;
#endif
}
#define SMEM_DESC_BASE_SW128 \
    ((uint64_t(2) << 61) | (uint64_t(1) << 46) | (uint64_t(64) << 32) | (uint64_t(1) << 16))
__device__ __forceinline__ uint64_t make_desc(uint32_t addr) {
    return SMEM_DESC_BASE_SW128 | ((uint64_t)(addr >> 4) & 0x3FFF);
}

// fp32 pair -> packed bf16x2 hi, residual packed bf16x2 lo
__device__ __forceinline__ uint32_t bf2_hi_lo(float a, float b, uint32_t& lo) {
    uint32_t hi;
    asm("cvt.rn.bf16x2.f32 %0, %1, %2;" : "=r"(hi) : "f"(b), "f"(a));
    __nv_bfloat162 h = *(__nv_bfloat162*)&hi;
    float ra = a - __bfloat162float(h.x);
    float rb = b - __bfloat162float(h.y);
    asm("cvt.rn.bf16x2.f32 %0, %1, %2;" : "=r"(lo) : "f"(rb), "f"(ra));
    return hi;
}
__device__ __forceinline__ uint32_t pack2(float a, float b) {
    uint32_t r;
    asm("cvt.rn.bf16x2.f32 %0, %1, %2;" : "=r"(r) : "f"(b), "f"(a));
    return r;
}

// ---------------- W -> bf16 hi/lo (tiny, once) -----------------------------
__global__ void convert_W(const float* __restrict__ W) {
    size_t i = ((size_t)blockIdx.x * 256 + threadIdx.x) * 4;
    float4 v = *(const float4*)(W + i);
    uint32_t l01, l23;
    uint32_t h01 = bf2_hi_lo(v.x, v.y, l01);
    uint32_t h23 = bf2_hi_lo(v.z, v.w, l23);
    *(uint2*)((uint16_t*)g_Whi + i) = make_uint2(h01, h23);
    *(uint2*)((uint16_t*)g_Wlo + i) = make_uint2(l01, l23);
}

// ======================= tcgen05 GEMM ======================================
// Per CTA: M=128, N=512 (two N=256 MMAs into 512 TMEM cols).
// 16 chunk-iterations of K=64:
//   pass1 (it 0..7):  load x fp32 -> Ahi+Alo smem, B=Whi; issue hi*Whi + lo*Whi
//   pass2 (it 8..15): load x fp32 -> Ahi smem,     B=Wlo; issue hi*Wlo
// Stage = Ahi 16K | Alo 16K | B 64K = 96KB, double-buffered.
#define BK 64
#define NITER 16
#define SM_S0 1024u
#define SM_S1 99328u            // 1024 + 98304
#define SM_TOTAL 197632         // 1024 + 2*98304
// idesc: dtype=F32, atype=BF16, btype=BF16, N=256, M=128
#define GEMM_IDESC ((1u << 4) | (1u << 7) | (1u << 10) | (32u << 17) | (8u << 24))

__global__ __launch_bounds__(256, 1)
void gemm_tc(const float* __restrict__ xa, const float* __restrict__ bias)
{
    extern __shared__ char smem[];
    const uint32_t sb = smem_u32(smem);
    const int tid = threadIdx.x;
    const int wid = tid >> 5;
    const int lid = tid & 31;
    const int m0 = blockIdx.x * 128;

    if (wid == 0) {
        tc_alloc(sb + 0, 512);
        tc_relinq();
    }
    if (tid == 0) mbar_init(sb + 8, 1);
    __syncthreads();
    uint32_t tbase;
    asm volatile("ld.shared.b32 %0, [%1];" : "=r"(tbase) : "r"(sb + 0));

    // A loader: fp32 -> bf16 hi(/lo) into SW128-swizzled smem
    auto load_a = [&](int k0, char* ahib, char* alob, bool wantlo) {
#pragma unroll
        for (int i = 0; i < 4; i++) {                  // 128 rows x 8 units
            int idx = i * 256 + tid;
            int row = idx >> 3, u = idx & 7;
            const float* s = xa + (size_t)(m0 + row) * DIN + k0 + u * 8;
            float4 f0 = *(const float4*)s;
            float4 f1 = *(const float4*)(s + 4);
            uint32_t l0, l1, l2, l3;
            uint4 hv;
            hv.x = bf2_hi_lo(f0.x, f0.y, l0);
            hv.y = bf2_hi_lo(f0.z, f0.w, l1);
            hv.z = bf2_hi_lo(f1.x, f1.y, l2);
            hv.w = bf2_hi_lo(f1.z, f1.w, l3);
            int off = row * 128 + ((u ^ (row & 7)) * 16);
            *(uint4*)(ahib + off) = hv;
            if (wantlo) *(uint4*)(alob + off) = make_uint4(l0, l1, l2, l3);
        }
    };
    auto load_b = [&](const __nv_bfloat16* Bsrc, int k0, char* bbuf) {
#pragma unroll
        for (int i = 0; i < 16; i++) {                 // 512 rows x 8 units
            int idx = i * 256 + tid;
            int row = idx >> 3, u = idx & 7;
            uint4 v = *(const uint4*)(Bsrc + (size_t)row * DIN + k0 + u * 8);
            *(uint4*)(bbuf + row * 128 + ((u ^ (row & 7)) * 16)) = v;
        }
    };
    auto load_chunk = [&](int it, int bufsel) {
        char* base = smem + (bufsel ? SM_S1 : SM_S0);
        if (it < 8) {
            load_a(it * BK, base, base + 16384, true);
            load_b(g_Whi, it * BK, base + 32768);
        } else {
            load_a((it - 8) * BK, base, base + 16384, false);
            load_b(g_Wlo, (it - 8) * BK, base + 32768);
        }
    };

    load_chunk(0, 0);
    __syncthreads();

    for (int it = 0; it < NITER; it++) {
        const int bs = it & 1;
        if (wid == 0) {
            fence_async_smem();
            if (elect_one()) {
                uint32_t s0 = sb + (bs ? SM_S1 : SM_S0);
                uint64_t adh = make_desc(s0);
                uint64_t adl = make_desc(s0 + 16384u);
                uint64_t bd0 = make_desc(s0 + 32768u);
                uint64_t bd1 = make_desc(s0 + 65536u);
                if (it < 8) {
#pragma unroll
                    for (int ks = 0; ks < 4; ks++) {
                        uint32_t en = (it == 0 && ks == 0) ? 0u : 1u;
                        mma_f16_ss(tbase + 0,   adh + ks * 2, bd0 + ks * 2, GEMM_IDESC, en);
                        mma_f16_ss(tbase + 256, adh + ks * 2, bd1 + ks * 2, GEMM_IDESC, en);
                        mma_f16_ss(tbase + 0,   adl + ks * 2, bd0 + ks * 2, GEMM_IDESC, 1u);
                        mma_f16_ss(tbase + 256, adl + ks * 2, bd1 + ks * 2, GEMM_IDESC, 1u);
                    }
                } else {
#pragma unroll
                    for (int ks = 0; ks < 4; ks++) {
                        mma_f16_ss(tbase + 0,   adh + ks * 2, bd0 + ks * 2, GEMM_IDESC, 1u);
                        mma_f16_ss(tbase + 256, adh + ks * 2, bd1 + ks * 2, GEMM_IDESC, 1u);
                    }
                }
                tc_commit(sb + 8);
            }
        }
        if (it + 1 < NITER) load_chunk(it + 1, bs ^ 1);
#if TC_OK
        mbar_wait(sb + 8, it & 1);
#endif
        __syncthreads();
    }

    tc_fence_after();
    // epilogue: warps 0-3 read 128 lanes x 512 cols, add bias, store
    if (wid < 4) {
        const int m = m0 + wid * 32 + lid;
        float* dst = g_Wx + (size_t)m * HH;
#pragma unroll 1
        for (int c0 = 0; c0 < HH; c0 += 32) {
            uint32_t r[32];
            ldtm_x32(r, tbase + c0);
            tc_wait_ld();
#pragma unroll
            for (int j = 0; j < 32; j += 4) {
                float4 bv = *(const float4*)(bias + c0 + j);
                float4 o;
                o.x = __uint_as_float(r[j + 0]) + bv.x;
                o.y = __uint_as_float(r[j + 1]) + bv.y;
                o.z = __uint_as_float(r[j + 2]) + bv.z;
                o.w = __uint_as_float(r[j + 3]) + bv.w;
                *(float4*)(dst + c0 + j) = o;
            }
        }
    }
    __syncthreads();
    if (wid == 0) {
        tc_dealloc(tbase, 512);
    }
}

// ---------------- Fused: chunk carries (raw) + BN stat partials ------------
// Carry recurrence is linear, so it runs on RAW Wx using only alpha:
//   end_raw = sum_t (1-a) a^(L-1-t) w_t ; BN affine applied later in combine.
__global__ __launch_bounds__(128)
void carry_stats(const float* __restrict__ alpha)
{
    const int k = blockIdx.x, b = blockIdx.y, tid = threadIdx.x;
    const int h4 = tid * 4;
    float4 av = *(const float4*)(alpha + h4);
    float4 a;
    a.x = fminf(fmaxf(av.x, ALPHA_LO), ALPHA_HI);
    a.y = fminf(fmaxf(av.y, ALPHA_LO), ALPHA_HI);
    a.z = fminf(fmaxf(av.z, ALPHA_LO), ALPHA_HI);
    a.w = fminf(fmaxf(av.w, ALPHA_LO), ALPHA_HI);
    float4 oma = {1.f - a.x, 1.f - a.y, 1.f - a.z, 1.f - a.w};
    float4 ut = {0.f, 0.f, 0.f, 0.f};
    float4 s = {0.f, 0.f, 0.f, 0.f};
    float4 q = {0.f, 0.f, 0.f, 0.f};
    const float* src = g_Wx + ((size_t)b * Tt + (size_t)k * LCHUNK) * HH + h4;
#pragma unroll 10
    for (int t = 0; t < LCHUNK; t++) {
        float4 w = *(const float4*)(src + (size_t)t * HH);
        s.x += w.x; s.y += w.y; s.z += w.z; s.w += w.w;
        q.x = fmaf(w.x, w.x, q.x); q.y = fmaf(w.y, w.y, q.y);
        q.z = fmaf(w.z, w.z, q.z); q.w = fmaf(w.w, w.w, q.w);
        ut.x = fmaf(a.x, ut.x, oma.x * w.x);
        ut.y = fmaf(a.y, ut.y, oma.y * w.y);
        ut.z = fmaf(a.z, ut.z, oma.z * w.z);
        ut.w = fmaf(a.w, ut.w, oma.w * w.w);
    }
    const size_t idx = (size_t)(k * Bb + b) * HH + h4;
    *(float4*)(g_chunkend + idx) = ut;
    *(float4*)(g_part_sum + idx) = s;
    *(float4*)(g_part_sq + idx) = q;
}

// ---------------- Stats reduce: 1280 -> 40 ---------------------------------
__global__ void stats_reduce()
{
    const int h = threadIdx.x;
    const int p0 = blockIdx.x * 32;
    float s = 0.f, q = 0.f;
#pragma unroll 8
    for (int i = 0; i < 32; i++) {
        s += g_part_sum[(size_t)(p0 + i) * HH + h];
        q += g_part_sq[(size_t)(p0 + i) * HH + h];
    }
    g_red_sum[blockIdx.x * HH + h] = s;
    g_red_sq[blockIdx.x * HH + h] = q;
}

// ---------------- BN params ------------------------------------------------
__global__ void bn_params(const float* __restrict__ alpha,
                          const float* __restrict__ gamma,
                          const float* __restrict__ beta)
{
    const int h = threadIdx.x;
    float s = 0.f, q = 0.f;
    for (int p = 0; p < NRED; p++) {
        s += g_red_sum[p * HH + h];
        q += g_red_sq[p * HH + h];
    }
    const float invN = 1.0f / (float)MM;
    float mean = s * invN;
    float var = q * invN - mean * mean;
    float rs = rsqrtf(var + BN_EPS);
    float gg = gamma[h] * rs;
    float cc = beta[h] - mean * gg;
    float a = fminf(fmaxf(alpha[h], ALPHA_LO), ALPHA_HI);
    float aL = 1.0f;
    for (int i = 0; i < LCHUNK; i++) aL *= a;
    g_pa[h] = a;
    g_poma[h] = 1.0f - a;
    g_pg[h] = gg;
    g_pc[h] = cc;
    g_paL[h] = aL;
}

// ---------------- Combine: propagate BN-corrected chunk-start states -------
__global__ void combine_carries(const float* __restrict__ ut0)
{
    const int b = blockIdx.x, h = threadIdx.x;
    const float aL = g_paL[h];
    const float gg = g_pg[h];
    const float ccS = g_pc[h] * (1.0f - aL);   // c * (1-a)*sum a^i over chunk
    float s = ut0[b * HH + h];
    g_start[(size_t)b * HH + h] = s;
    for (int k = 0; k < NCHUNK - 1; k++) {
        float endv = fmaf(gg, g_chunkend[((size_t)k * Bb + b) * HH + h], ccS);
        s = fmaf(aL, s, endv);
        g_start[((size_t)(k + 1) * Bb + b) * HH + h] = s;
    }
}

// ---------------- Scan: exact recurrence + softmax accumulation ------------
__global__ __launch_bounds__(128)
void scan_softmax()
{
    __shared__ float smax[4];
    __shared__ float ssum[4];
    const int k = blockIdx.x, b = blockIdx.y, tid = threadIdx.x;
    const int lane = tid & 31, wid = tid >> 5;
    const int h4 = tid * 4;
    float4 a   = *(const float4*)(g_pa + h4);
    float4 oma = *(const float4*)(g_poma + h4);
    float4 gg  = *(const float4*)(g_pg + h4);
    float4 cc  = *(const float4*)(g_pc + h4);
    float4 ut  = *(const float4*)(g_start + ((size_t)k * Bb + b) * HH + h4);
    float4 acc = {0.f, 0.f, 0.f, 0.f};
    const float* src = g_Wx + ((size_t)b * Tt + (size_t)k * LCHUNK) * HH + h4;

    for (int t = 0; t < LCHUNK; t++) {
        float4 w = *(const float4*)(src + (size_t)t * HH);
        float w0 = fmaf(gg.x, w.x, cc.x);
        float w1 = fmaf(gg.y, w.y, cc.y);
        float w2 = fmaf(gg.z, w.z, cc.z);
        float w3 = fmaf(gg.w, w.w, cc.w);
        ut.x = fmaf(a.x, ut.x, oma.x * w0);
        ut.y = fmaf(a.y, ut.y, oma.y * w1);
        ut.z = fmaf(a.z, ut.z, oma.z * w2);
        ut.w = fmaf(a.w, ut.w, oma.w * w3);

        float m = fmaxf(fmaxf(ut.x, ut.y), fmaxf(ut.z, ut.w));
#pragma unroll
        for (int o = 16; o; o >>= 1) m = fmaxf(m, __shfl_xor_sync(0xffffffffu, m, o));
        if (lane == 0) smax[wid] = m;
        __syncthreads();
        float Mx = fmaxf(fmaxf(smax[0], smax[1]), fmaxf(smax[2], smax[3]));

        float e0 = __expf(ut.x - Mx);
        float e1 = __expf(ut.y - Mx);
        float e2 = __expf(ut.z - Mx);
        float e3 = __expf(ut.w - Mx);
        float sv = (e0 + e1) + (e2 + e3);
#pragma unroll
        for (int o = 16; o; o >>= 1) sv += __shfl_xor_sync(0xffffffffu, sv, o);
        if (lane == 0) ssum[wid] = sv;
        __syncthreads();
        float inv = 1.0f / ((ssum[0] + ssum[1]) + (ssum[2] + ssum[3]));

        acc.x = fmaf(e0, inv, acc.x);
        acc.y = fmaf(e1, inv, acc.y);
        acc.z = fmaf(e2, inv, acc.z);
        acc.w = fmaf(e3, inv, acc.w);
    }
    *(float4*)(g_accpart + ((size_t)k * Bb + b) * HH + h4) = acc;
}

// ---------------- Final deterministic reduction over chunks ----------------
__global__ void final_sum(float* __restrict__ out)
{
    const int b = blockIdx.x, h = threadIdx.x;
    float s = 0.f;
    for (int k = 0; k < NCHUNK; k++)
        s += g_accpart[((size_t)k * Bb + b) * HH + h];
    out[b * HH + h] = s;
}

// ---------------- launch ---------------------------------------------------
extern "C" void kernel_launch(void* const* d_in, const int* in_sizes, int n_in,
                              void* d_out, int out_size)
{
    const float* x     = (const float*)d_in[0];
    const float* W     = (const float*)d_in[1];
    const float* bias  = (const float*)d_in[2];
    const float* alpha = (const float*)d_in[3];
    const float* gamma = (const float*)d_in[4];
    const float* beta  = (const float*)d_in[5];
    const float* ut0   = (const float*)d_in[6];
    float* out = (float*)d_out;

    cudaFuncSetAttribute(gemm_tc, cudaFuncAttributeMaxDynamicSharedMemorySize, SM_TOTAL);

    convert_W<<<(HH * DIN) / (256 * 4), 256>>>(W);
    gemm_tc<<<MM / 128, 256, SM_TOTAL>>>(x, bias);
    carry_stats<<<dim3(NCHUNK, Bb), 128>>>(alpha);
    stats_reduce<<<NRED, HH>>>();
    bn_params<<<1, HH>>>(alpha, gamma, beta);
    combine_carries<<<Bb, HH>>>(ut0);
    scan_softmax<<<dim3(NCHUNK, Bb), 128>>>();
    final_sum<<<Bb, HH>>>(out);
}